// round 1
// baseline (speedup 1.0000x reference)
#include <cuda_runtime.h>
#include <cuda_bf16.h>

#define UNITS 128
#define MAX_NODES 100000

// Scratch for h = x @ W (allocation-free: __device__ global)
__device__ float g_h[(size_t)MAX_NODES * UNITS];

// ---------------------------------------------------------------------------
// Kernel 1: h = x @ W, and out_base = (1+eps)*h + bias  (written to d_out)
// Tile: 64 rows x 128 cols per block, 256 threads, each thread 4x8 micro-tile.
// ---------------------------------------------------------------------------
__global__ void __launch_bounds__(256) gin_gemm_kernel(
    const float* __restrict__ x, const float* __restrict__ W,
    const float* __restrict__ bias, const float* __restrict__ eps,
    float* __restrict__ out_base, int nrows)
{
    __shared__ float xs[16][64];    // [k][m]
    __shared__ float ws[16][128];   // [k][n]

    const int tid = threadIdx.x;
    const int tr  = tid >> 4;       // 0..15 -> rows tr*4 .. tr*4+3
    const int tc  = tid & 15;       // 0..15 -> cols tc*8 .. tc*8+7
    const int row0 = blockIdx.x * 64;

    float acc[4][8];
#pragma unroll
    for (int i = 0; i < 4; i++)
#pragma unroll
        for (int j = 0; j < 8; j++) acc[i][j] = 0.0f;

    for (int k0 = 0; k0 < UNITS; k0 += 16) {
        // load x tile: 64 rows x 16 k
#pragma unroll
        for (int i = 0; i < 4; i++) {
            int e = tid + i * 256;
            int m = e >> 4, k = e & 15;
            int gr = row0 + m;
            xs[k][m] = (gr < nrows) ? x[(size_t)gr * UNITS + k0 + k] : 0.0f;
        }
        // load W tile: 16 k x 128 n (fully coalesced)
#pragma unroll
        for (int i = 0; i < 8; i++) {
            int e = tid + i * 256;
            int k = e >> 7, n = e & 127;
            ws[k][n] = W[(size_t)(k0 + k) * UNITS + n];
        }
        __syncthreads();

#pragma unroll
        for (int k = 0; k < 16; k++) {
            float4 a  = *(const float4*)&xs[k][tr * 4];
            float4 b0 = *(const float4*)&ws[k][tc * 8];
            float4 b1 = *(const float4*)&ws[k][tc * 8 + 4];
            float av[4] = {a.x, a.y, a.z, a.w};
            float bv[8] = {b0.x, b0.y, b0.z, b0.w, b1.x, b1.y, b1.z, b1.w};
#pragma unroll
            for (int i = 0; i < 4; i++)
#pragma unroll
                for (int j = 0; j < 8; j++)
                    acc[i][j] = fmaf(av[i], bv[j], acc[i][j]);
        }
        __syncthreads();
    }

    const float e1 = 1.0f + eps[0];
    float bv[8];
#pragma unroll
    for (int j = 0; j < 8; j++) bv[j] = bias[tc * 8 + j];

#pragma unroll
    for (int i = 0; i < 4; i++) {
        int gr = row0 + tr * 4 + i;
        if (gr >= nrows) break;
        size_t base = (size_t)gr * UNITS + tc * 8;
        float4 h0, h1, o0, o1;
        h0.x = acc[i][0]; h0.y = acc[i][1]; h0.z = acc[i][2]; h0.w = acc[i][3];
        h1.x = acc[i][4]; h1.y = acc[i][5]; h1.z = acc[i][6]; h1.w = acc[i][7];
        o0.x = fmaf(e1, acc[i][0], bv[0]); o0.y = fmaf(e1, acc[i][1], bv[1]);
        o0.z = fmaf(e1, acc[i][2], bv[2]); o0.w = fmaf(e1, acc[i][3], bv[3]);
        o1.x = fmaf(e1, acc[i][4], bv[4]); o1.y = fmaf(e1, acc[i][5], bv[5]);
        o1.z = fmaf(e1, acc[i][6], bv[6]); o1.w = fmaf(e1, acc[i][7], bv[7]);
        *(float4*)&g_h[base]        = h0;
        *(float4*)&g_h[base + 4]    = h1;
        *(float4*)&out_base[base]     = o0;
        *(float4*)&out_base[base + 4] = o1;
    }
}

// ---------------------------------------------------------------------------
// Kernel 2: out[row[e]] += vals[e] * h[col[e]]   (warp per edge, 32 edges/warp
// batch with coalesced metadata loads + shfl broadcast, float4 gather,
// vector red.global.add.v4.f32)
// ---------------------------------------------------------------------------
__global__ void __launch_bounds__(256) gin_edge_kernel(
    const float* __restrict__ vals, const int* __restrict__ row,
    const int* __restrict__ col, float* __restrict__ out, int nedges)
{
    const int warpId = (blockIdx.x * blockDim.x + threadIdx.x) >> 5;
    const int lane   = threadIdx.x & 31;

    const int ebase = warpId * 32;
    if (ebase >= nedges) return;

    const int eIdx = ebase + lane;
    int   my_c = -1, my_r = -1;
    float my_v = 0.0f;
    if (eIdx < nedges) {
        my_c = col[eIdx];
        my_r = row[eIdx];
        my_v = vals[eIdx];
    }

    const int cnt = min(32, nedges - ebase);
    for (int e = 0; e < cnt; e++) {
        int   c = __shfl_sync(0xffffffffu, my_c, e);
        int   r = __shfl_sync(0xffffffffu, my_r, e);
        float v = __shfl_sync(0xffffffffu, my_v, e);

        float4 hv = *(const float4*)&g_h[(size_t)c * UNITS + lane * 4];
        float4 o;
        o.x = hv.x * v; o.y = hv.y * v; o.z = hv.z * v; o.w = hv.w * v;
        float* dst = out + (size_t)r * UNITS + lane * 4;
        asm volatile("red.global.add.v4.f32 [%0], {%1, %2, %3, %4};"
                     :: "l"(dst), "f"(o.x), "f"(o.y), "f"(o.z), "f"(o.w)
                     : "memory");
    }
}

// ---------------------------------------------------------------------------
// Kernel 3: out = relu(out)
// ---------------------------------------------------------------------------
__global__ void __launch_bounds__(256) gin_relu_kernel(float* __restrict__ out, int n4)
{
    int idx = blockIdx.x * blockDim.x + threadIdx.x;
    int stride = gridDim.x * blockDim.x;
    for (int i = idx; i < n4; i += stride) {
        float4 v = ((float4*)out)[i];
        v.x = fmaxf(v.x, 0.0f); v.y = fmaxf(v.y, 0.0f);
        v.z = fmaxf(v.z, 0.0f); v.w = fmaxf(v.w, 0.0f);
        ((float4*)out)[i] = v;
    }
}

extern "C" void kernel_launch(void* const* d_in, const int* in_sizes, int n_in,
                              void* d_out, int out_size)
{
    const float* x    = (const float*)d_in[0];
    const float* W    = (const float*)d_in[1];
    const float* bias = (const float*)d_in[2];
    const float* eps  = (const float*)d_in[3];
    const float* vals = (const float*)d_in[4];
    const int*   row  = (const int*)d_in[5];
    const int*   col  = (const int*)d_in[6];
    float* out = (float*)d_out;

    const int nnodes = in_sizes[0] / UNITS;
    const int nedges = in_sizes[4];

    // Kernel 1: GEMM + base epilogue (writes g_h and out base)
    int gemm_blocks = (nnodes + 63) / 64;
    gin_gemm_kernel<<<gemm_blocks, 256>>>(x, W, bias, eps, out, nnodes);

    // Kernel 2: edge aggregation via vector atomics
    int nwarps = (nedges + 31) / 32;
    int edge_blocks = (nwarps + 7) / 8;   // 8 warps per block
    gin_edge_kernel<<<edge_blocks, 256>>>(vals, row, col, out, nedges);

    // Kernel 3: relu in place
    int n4 = out_size / 4;
    int relu_blocks = (n4 + 255) / 256;
    if (relu_blocks > 8192) relu_blocks = 8192;
    gin_relu_kernel<<<relu_blocks, 256>>>(out, n4);
}

// round 2
// speedup vs baseline: 1.5586x; 1.5586x over previous
#include <cuda_runtime.h>

#define UNITS 128
#define MAX_NODES 100000
#define MAX_EDGES 1600000

// ------------------------- static scratch (no allocs) -----------------------
__device__ float g_h[(size_t)MAX_NODES * UNITS];   // h = x @ W
__device__ int2  g_perm[MAX_EDGES];                // (col, val_bits) sorted by row
__device__ int   g_counts[MAX_NODES];
__device__ int   g_starts[MAX_NODES];
__device__ int   g_cursor[MAX_NODES];
__device__ int   g_bsums[512];

// packed f32x2 FMA (Blackwell; ptxas never emits from C++)
#define FMA2(acc, a, b) \
    asm("fma.rn.f32x2 %0, %1, %2, %0;" : "+l"(acc) : "l"(a), "l"(b))
#define PACKDUP(dst, f) \
    asm("mov.b64 %0, {%1, %1};" : "=l"(dst) : "f"(f))

__device__ __forceinline__ float f2lo(unsigned long long v) {
    return __uint_as_float((unsigned)(v & 0xffffffffull));
}
__device__ __forceinline__ float f2hi(unsigned long long v) {
    return __uint_as_float((unsigned)(v >> 32));
}

// ---------------------------------------------------------------------------
// Kernel 1: h = x @ W ; out_base = (1+eps)*h + bias
// 128x128 block tile, 256 threads, 8x8 per thread, f32x2 packed FMA,
// register-prefetch double buffering over K chunks of 16.
// ---------------------------------------------------------------------------
__global__ void __launch_bounds__(256, 2) gin_gemm_kernel(
    const float* __restrict__ x, const float* __restrict__ W,
    const float* __restrict__ bias, const float* __restrict__ eps,
    float* __restrict__ out_base, int nrows)
{
    __shared__ float xs[16][128];   // [k][m]
    __shared__ float ws[16][128];   // [k][n]

    const int tid = threadIdx.x;
    const int tr  = tid >> 4;       // 0..15 -> rows tr*8..+7
    const int tc  = tid & 15;       // 0..15 -> cols tc*8..+7
    const int row0 = blockIdx.x * 128;

    // staging registers for prefetch
    float4 xreg[2], wreg[2];

    // pair accumulators: accp[i][j] holds rows (tr*8+2i, tr*8+2i+1), col tc*8+j
    unsigned long long accp[4][8];
#pragma unroll
    for (int i = 0; i < 4; i++)
#pragma unroll
        for (int j = 0; j < 8; j++) accp[i][j] = 0ull;

    // ---- load helpers (K chunk = 16) ----
    // x tile: 128 rows x 16 k = 512 float4, 2 per thread
    // thread t, it: idx = t + it*256 -> r = idx>>2, q = idx&3, k = q*4
    // w tile: 16 k x 128 n = 512 float4: k = idx>>5, n = (idx&31)*4
#define LOAD_CHUNK(k0)                                                        \
    {                                                                          \
        _Pragma("unroll")                                                      \
        for (int it = 0; it < 2; it++) {                                       \
            int idx = tid + it * 256;                                          \
            int r = idx >> 2, q = idx & 3;                                     \
            int gr = row0 + r;                                                 \
            if (gr < nrows)                                                    \
                xreg[it] = *(const float4*)&x[(size_t)gr * UNITS + (k0) + q * 4]; \
            else                                                               \
                xreg[it] = make_float4(0.f, 0.f, 0.f, 0.f);                    \
            int k = idx >> 5, n = (idx & 31) * 4;                              \
            wreg[it] = *(const float4*)&W[(size_t)((k0) + k) * UNITS + n];     \
        }                                                                      \
    }

#define STORE_CHUNK()                                                          \
    {                                                                          \
        _Pragma("unroll")                                                      \
        for (int it = 0; it < 2; it++) {                                       \
            int idx = tid + it * 256;                                          \
            int r = idx >> 2, q = idx & 3;                                     \
            xs[q * 4 + 0][r] = xreg[it].x;                                     \
            xs[q * 4 + 1][r] = xreg[it].y;                                     \
            xs[q * 4 + 2][r] = xreg[it].z;                                     \
            xs[q * 4 + 3][r] = xreg[it].w;                                     \
            int k = idx >> 5, n = (idx & 31) * 4;                              \
            *(float4*)&ws[k][n] = wreg[it];                                    \
        }                                                                      \
    }

    LOAD_CHUNK(0);

    for (int c = 0; c < 8; c++) {
        __syncthreads();           // previous compute done, smem free
        STORE_CHUNK();
        __syncthreads();
        if (c < 7) LOAD_CHUNK((c + 1) * 16);

#pragma unroll
        for (int k = 0; k < 16; k++) {
            ulonglong2 a01 = *(const ulonglong2*)&xs[k][tr * 8];
            ulonglong2 a23 = *(const ulonglong2*)&xs[k][tr * 8 + 4];
            float4 b0 = *(const float4*)&ws[k][tc * 8];
            float4 b1 = *(const float4*)&ws[k][tc * 8 + 4];
            unsigned long long av[4] = {a01.x, a01.y, a23.x, a23.y};
            unsigned long long bb[8];
            PACKDUP(bb[0], b0.x); PACKDUP(bb[1], b0.y);
            PACKDUP(bb[2], b0.z); PACKDUP(bb[3], b0.w);
            PACKDUP(bb[4], b1.x); PACKDUP(bb[5], b1.y);
            PACKDUP(bb[6], b1.z); PACKDUP(bb[7], b1.w);
#pragma unroll
            for (int i = 0; i < 4; i++)
#pragma unroll
                for (int j = 0; j < 8; j++)
                    FMA2(accp[i][j], av[i], bb[j]);
        }
    }

    // epilogue
    const float e1 = 1.0f + eps[0];
    float4 bv0 = *(const float4*)&bias[tc * 8];
    float4 bv1 = *(const float4*)&bias[tc * 8 + 4];

#pragma unroll
    for (int i = 0; i < 4; i++) {
#pragma unroll
        for (int half = 0; half < 2; half++) {
            int gr = row0 + tr * 8 + 2 * i + half;
            if (gr >= nrows) continue;
            float h[8];
#pragma unroll
            for (int j = 0; j < 8; j++)
                h[j] = half ? f2hi(accp[i][j]) : f2lo(accp[i][j]);
            size_t base = (size_t)gr * UNITS + tc * 8;
            float4 h0 = make_float4(h[0], h[1], h[2], h[3]);
            float4 h1 = make_float4(h[4], h[5], h[6], h[7]);
            float4 o0, o1;
            o0.x = fmaf(e1, h[0], bv0.x); o0.y = fmaf(e1, h[1], bv0.y);
            o0.z = fmaf(e1, h[2], bv0.z); o0.w = fmaf(e1, h[3], bv0.w);
            o1.x = fmaf(e1, h[4], bv1.x); o1.y = fmaf(e1, h[5], bv1.y);
            o1.z = fmaf(e1, h[6], bv1.z); o1.w = fmaf(e1, h[7], bv1.w);
            *(float4*)&g_h[base]          = h0;
            *(float4*)&g_h[base + 4]      = h1;
            *(float4*)&out_base[base]     = o0;
            *(float4*)&out_base[base + 4] = o1;
        }
    }
}

// ---------------------------------------------------------------------------
// Counting sort of edges by destination row
// ---------------------------------------------------------------------------
__global__ void __launch_bounds__(256) zero_counts_kernel(int n)
{
    int i = blockIdx.x * blockDim.x + threadIdx.x;
    int stride = gridDim.x * blockDim.x;
    for (; i < n; i += stride) g_counts[i] = 0;
}

__global__ void __launch_bounds__(256) hist_kernel(const int* __restrict__ row, int nedges)
{
    int i = blockIdx.x * blockDim.x + threadIdx.x;
    int stride = gridDim.x * blockDim.x;
    for (; i < nedges; i += stride) atomicAdd(&g_counts[row[i]], 1);
}

// per-block exclusive scan of counts -> g_starts (local), block totals -> g_bsums
__global__ void __launch_bounds__(256) scan_block_kernel(int n)
{
    __shared__ int sh[256];
    int i = blockIdx.x * 256 + threadIdx.x;
    int v = (i < n) ? g_counts[i] : 0;
    sh[threadIdx.x] = v;
    __syncthreads();
#pragma unroll
    for (int off = 1; off < 256; off <<= 1) {
        int t = (threadIdx.x >= off) ? sh[threadIdx.x - off] : 0;
        __syncthreads();
        sh[threadIdx.x] += t;
        __syncthreads();
    }
    if (i < n) g_starts[i] = sh[threadIdx.x] - v;   // exclusive
    if (threadIdx.x == 255) g_bsums[blockIdx.x] = sh[255];
}

__global__ void __launch_bounds__(512) scan_sums_kernel(int nb)
{
    __shared__ int sh[512];
    int t = threadIdx.x;
    int v = (t < nb) ? g_bsums[t] : 0;
    sh[t] = v;
    __syncthreads();
#pragma unroll
    for (int off = 1; off < 512; off <<= 1) {
        int u = (t >= off) ? sh[t - off] : 0;
        __syncthreads();
        sh[t] += u;
        __syncthreads();
    }
    if (t < nb) g_bsums[t] = sh[t] - v;   // exclusive
}

__global__ void __launch_bounds__(256) finalize_starts_kernel(int n)
{
    int i = blockIdx.x * blockDim.x + threadIdx.x;
    if (i < n) {
        int s = g_starts[i] + g_bsums[i >> 8];
        g_starts[i] = s;
        g_cursor[i] = s;
    }
}

__global__ void __launch_bounds__(256) scatter_kernel(
    const float* __restrict__ vals, const int* __restrict__ row,
    const int* __restrict__ col, int nedges)
{
    int i = blockIdx.x * blockDim.x + threadIdx.x;
    int stride = gridDim.x * blockDim.x;
    for (; i < nedges; i += stride) {
        int r = row[i];
        int p = atomicAdd(&g_cursor[r], 1);
        g_perm[p] = make_int2(col[i], __float_as_int(vals[i]));
    }
}

// ---------------------------------------------------------------------------
// Warp-per-node aggregation + fused relu. Each output row written exactly once.
// ---------------------------------------------------------------------------
__global__ void __launch_bounds__(256) gin_agg_kernel(float* __restrict__ out, int nnodes)
{
    int warpId = (blockIdx.x * blockDim.x + threadIdx.x) >> 5;
    if (warpId >= nnodes) return;
    const int lane = threadIdx.x & 31;

    const int s   = g_starts[warpId];
    const int cnt = g_counts[warpId];

    float4 acc0 = make_float4(0.f, 0.f, 0.f, 0.f);
    float4 acc1 = make_float4(0.f, 0.f, 0.f, 0.f);

    int e = s;
    const int end = s + cnt;
    for (; e + 2 <= end; e += 2) {
        int2 p0 = g_perm[e];
        int2 p1 = g_perm[e + 1];
        float4 h0 = *(const float4*)&g_h[(size_t)p0.x * UNITS + lane * 4];
        float4 h1 = *(const float4*)&g_h[(size_t)p1.x * UNITS + lane * 4];
        float v0 = __int_as_float(p0.y);
        float v1 = __int_as_float(p1.y);
        acc0.x = fmaf(v0, h0.x, acc0.x); acc0.y = fmaf(v0, h0.y, acc0.y);
        acc0.z = fmaf(v0, h0.z, acc0.z); acc0.w = fmaf(v0, h0.w, acc0.w);
        acc1.x = fmaf(v1, h1.x, acc1.x); acc1.y = fmaf(v1, h1.y, acc1.y);
        acc1.z = fmaf(v1, h1.z, acc1.z); acc1.w = fmaf(v1, h1.w, acc1.w);
    }
    if (e < end) {
        int2 p0 = g_perm[e];
        float4 h0 = *(const float4*)&g_h[(size_t)p0.x * UNITS + lane * 4];
        float v0 = __int_as_float(p0.y);
        acc0.x = fmaf(v0, h0.x, acc0.x); acc0.y = fmaf(v0, h0.y, acc0.y);
        acc0.z = fmaf(v0, h0.z, acc0.z); acc0.w = fmaf(v0, h0.w, acc0.w);
    }

    float* dst = out + (size_t)warpId * UNITS + lane * 4;
    float4 o = *(float4*)dst;
    o.x = fmaxf(o.x + acc0.x + acc1.x, 0.f);
    o.y = fmaxf(o.y + acc0.y + acc1.y, 0.f);
    o.z = fmaxf(o.z + acc0.z + acc1.z, 0.f);
    o.w = fmaxf(o.w + acc0.w + acc1.w, 0.f);
    *(float4*)dst = o;
}

// ---------------------------------------------------------------------------
extern "C" void kernel_launch(void* const* d_in, const int* in_sizes, int n_in,
                              void* d_out, int out_size)
{
    const float* x    = (const float*)d_in[0];
    const float* W    = (const float*)d_in[1];
    const float* bias = (const float*)d_in[2];
    const float* eps  = (const float*)d_in[3];
    const float* vals = (const float*)d_in[4];
    const int*   row  = (const int*)d_in[5];
    const int*   col  = (const int*)d_in[6];
    float* out = (float*)d_out;

    const int nnodes = in_sizes[0] / UNITS;
    const int nedges = in_sizes[4];

    // 1. GEMM + base epilogue (writes g_h and out base)
    int gemm_blocks = (nnodes + 127) / 128;
    gin_gemm_kernel<<<gemm_blocks, 256>>>(x, W, bias, eps, out, nnodes);

    // 2. counting sort of edges by row
    int nscan = (nnodes + 255) / 256;
    zero_counts_kernel<<<nscan, 256>>>(nnodes);
    hist_kernel<<<1024, 256>>>(row, nedges);
    scan_block_kernel<<<nscan, 256>>>(nnodes);
    scan_sums_kernel<<<1, 512>>>(nscan);
    finalize_starts_kernel<<<nscan, 256>>>(nnodes);
    scatter_kernel<<<1024, 256>>>(vals, row, col, nedges);

    // 3. warp-per-node aggregation + fused relu
    int agg_blocks = (nnodes + 7) / 8;   // 8 warps (nodes) per block
    gin_agg_kernel<<<agg_blocks, 256>>>(out, nnodes);
}

// round 3
// speedup vs baseline: 1.6498x; 1.0586x over previous
#include <cuda_runtime.h>
#include <cuda_fp16.h>

#define UNITS 128
#define MAX_NODES 100000
#define MAX_EDGES 1600000

// ------------------------- static scratch (no allocs) -----------------------
// h = x @ W stored as fp16 (uint = packed half2), 64 uints per row
__device__ unsigned g_h16[(size_t)MAX_NODES * (UNITS / 2)];
__device__ int2  g_perm[MAX_EDGES];                // (col, val_bits) sorted by row
__device__ int   g_counts[MAX_NODES];
__device__ int   g_starts[MAX_NODES];
__device__ int   g_cursor[MAX_NODES];
__device__ int   g_bsums[512];

// packed f32x2 FMA (Blackwell; ptxas never emits from C++)
#define FMA2(acc, a, b) \
    asm("fma.rn.f32x2 %0, %1, %2, %0;" : "+l"(acc) : "l"(a), "l"(b))
#define PACKDUP(dst, f) \
    asm("mov.b64 %0, {%1, %1};" : "=l"(dst) : "f"(f))

__device__ __forceinline__ float f2lo(unsigned long long v) {
    return __uint_as_float((unsigned)(v & 0xffffffffull));
}
__device__ __forceinline__ float f2hi(unsigned long long v) {
    return __uint_as_float((unsigned)(v >> 32));
}
// pack two floats into half2 bits: lo = a, hi = b
__device__ __forceinline__ unsigned pack_h2(float a, float b) {
    unsigned r;
    asm("cvt.rn.f16x2.f32 %0, %1, %2;" : "=r"(r) : "f"(b), "f"(a));
    return r;
}
__device__ __forceinline__ float2 unpack_h2(unsigned u) {
    __half2 h = *(__half2*)&u;
    return __half22float2(h);
}

// ---------------------------------------------------------------------------
// Kernel 1: h = x @ W ; out_base = (1+eps)*h + bias (fp32), g_h16 = fp16(h)
// 128x128 block tile, 256 threads, 8x8 per thread, f32x2 packed FMA.
// ---------------------------------------------------------------------------
__global__ void __launch_bounds__(256, 2) gin_gemm_kernel(
    const float* __restrict__ x, const float* __restrict__ W,
    const float* __restrict__ bias, const float* __restrict__ eps,
    float* __restrict__ out_base, int nrows)
{
    __shared__ float xs[16][128];   // [k][m]
    __shared__ float ws[16][128];   // [k][n]

    const int tid = threadIdx.x;
    const int tr  = tid >> 4;       // rows tr*8..+7
    const int tc  = tid & 15;       // cols tc*8..+7
    const int row0 = blockIdx.x * 128;

    float4 xreg[2], wreg[2];

    unsigned long long accp[4][8];
#pragma unroll
    for (int i = 0; i < 4; i++)
#pragma unroll
        for (int j = 0; j < 8; j++) accp[i][j] = 0ull;

#define LOAD_CHUNK(k0)                                                        \
    {                                                                          \
        _Pragma("unroll")                                                      \
        for (int it = 0; it < 2; it++) {                                       \
            int idx = tid + it * 256;                                          \
            int r = idx >> 2, q = idx & 3;                                     \
            int gr = row0 + r;                                                 \
            if (gr < nrows)                                                    \
                xreg[it] = *(const float4*)&x[(size_t)gr * UNITS + (k0) + q * 4]; \
            else                                                               \
                xreg[it] = make_float4(0.f, 0.f, 0.f, 0.f);                    \
            int k = idx >> 5, n = (idx & 31) * 4;                              \
            wreg[it] = *(const float4*)&W[(size_t)((k0) + k) * UNITS + n];     \
        }                                                                      \
    }

#define STORE_CHUNK()                                                          \
    {                                                                          \
        _Pragma("unroll")                                                      \
        for (int it = 0; it < 2; it++) {                                       \
            int idx = tid + it * 256;                                          \
            int r = idx >> 2, q = idx & 3;                                     \
            xs[q * 4 + 0][r] = xreg[it].x;                                     \
            xs[q * 4 + 1][r] = xreg[it].y;                                     \
            xs[q * 4 + 2][r] = xreg[it].z;                                     \
            xs[q * 4 + 3][r] = xreg[it].w;                                     \
            int k = idx >> 5, n = (idx & 31) * 4;                              \
            *(float4*)&ws[k][n] = wreg[it];                                    \
        }                                                                      \
    }

    LOAD_CHUNK(0);

    for (int c = 0; c < 8; c++) {
        __syncthreads();
        STORE_CHUNK();
        __syncthreads();
        if (c < 7) LOAD_CHUNK((c + 1) * 16);

#pragma unroll
        for (int k = 0; k < 16; k++) {
            ulonglong2 a01 = *(const ulonglong2*)&xs[k][tr * 8];
            ulonglong2 a23 = *(const ulonglong2*)&xs[k][tr * 8 + 4];
            float4 b0 = *(const float4*)&ws[k][tc * 8];
            float4 b1 = *(const float4*)&ws[k][tc * 8 + 4];
            unsigned long long av[4] = {a01.x, a01.y, a23.x, a23.y};
            unsigned long long bb[8];
            PACKDUP(bb[0], b0.x); PACKDUP(bb[1], b0.y);
            PACKDUP(bb[2], b0.z); PACKDUP(bb[3], b0.w);
            PACKDUP(bb[4], b1.x); PACKDUP(bb[5], b1.y);
            PACKDUP(bb[6], b1.z); PACKDUP(bb[7], b1.w);
#pragma unroll
            for (int i = 0; i < 4; i++)
#pragma unroll
                for (int j = 0; j < 8; j++)
                    FMA2(accp[i][j], av[i], bb[j]);
        }
    }

    const float e1 = 1.0f + eps[0];
    float4 bv0 = *(const float4*)&bias[tc * 8];
    float4 bv1 = *(const float4*)&bias[tc * 8 + 4];

#pragma unroll
    for (int i = 0; i < 4; i++) {
#pragma unroll
        for (int half = 0; half < 2; half++) {
            int gr = row0 + tr * 8 + 2 * i + half;
            if (gr >= nrows) continue;
            float h[8];
#pragma unroll
            for (int j = 0; j < 8; j++)
                h[j] = half ? f2hi(accp[i][j]) : f2lo(accp[i][j]);

            // fp16 copy of h (4 packed half2 = 16B)
            uint4 hp;
            hp.x = pack_h2(h[0], h[1]);
            hp.y = pack_h2(h[2], h[3]);
            hp.z = pack_h2(h[4], h[5]);
            hp.w = pack_h2(h[6], h[7]);
            *(uint4*)&g_h16[(size_t)gr * (UNITS / 2) + tc * 4] = hp;

            // fp32 base: (1+eps)*h + bias
            size_t base = (size_t)gr * UNITS + tc * 8;
            float4 o0, o1;
            o0.x = fmaf(e1, h[0], bv0.x); o0.y = fmaf(e1, h[1], bv0.y);
            o0.z = fmaf(e1, h[2], bv0.z); o0.w = fmaf(e1, h[3], bv0.w);
            o1.x = fmaf(e1, h[4], bv1.x); o1.y = fmaf(e1, h[5], bv1.y);
            o1.z = fmaf(e1, h[6], bv1.z); o1.w = fmaf(e1, h[7], bv1.w);
            *(float4*)&out_base[base]     = o0;
            *(float4*)&out_base[base + 4] = o1;
        }
    }
}

// ---------------------------------------------------------------------------
// Counting sort of edges by destination row
// ---------------------------------------------------------------------------
__global__ void __launch_bounds__(256) zero_counts_kernel(int n)
{
    int i = blockIdx.x * blockDim.x + threadIdx.x;
    int stride = gridDim.x * blockDim.x;
    for (; i < n; i += stride) g_counts[i] = 0;
}

__global__ void __launch_bounds__(256) hist_kernel(const int* __restrict__ row, int nedges)
{
    int i = blockIdx.x * blockDim.x + threadIdx.x;
    int stride = gridDim.x * blockDim.x;
    for (; i < nedges; i += stride) atomicAdd(&g_counts[row[i]], 1);
}

__global__ void __launch_bounds__(256) scan_block_kernel(int n)
{
    __shared__ int sh[256];
    int i = blockIdx.x * 256 + threadIdx.x;
    int v = (i < n) ? g_counts[i] : 0;
    sh[threadIdx.x] = v;
    __syncthreads();
#pragma unroll
    for (int off = 1; off < 256; off <<= 1) {
        int t = (threadIdx.x >= off) ? sh[threadIdx.x - off] : 0;
        __syncthreads();
        sh[threadIdx.x] += t;
        __syncthreads();
    }
    if (i < n) g_starts[i] = sh[threadIdx.x] - v;   // exclusive
    if (threadIdx.x == 255) g_bsums[blockIdx.x] = sh[255];
}

__global__ void __launch_bounds__(512) scan_sums_kernel(int nb)
{
    __shared__ int sh[512];
    int t = threadIdx.x;
    int v = (t < nb) ? g_bsums[t] : 0;
    sh[t] = v;
    __syncthreads();
#pragma unroll
    for (int off = 1; off < 512; off <<= 1) {
        int u = (t >= off) ? sh[t - off] : 0;
        __syncthreads();
        sh[t] += u;
        __syncthreads();
    }
    if (t < nb) g_bsums[t] = sh[t] - v;   // exclusive
}

__global__ void __launch_bounds__(256) finalize_starts_kernel(int n)
{
    int i = blockIdx.x * blockDim.x + threadIdx.x;
    if (i < n) {
        int s = g_starts[i] + g_bsums[i >> 8];
        g_starts[i] = s;
        g_cursor[i] = s;
    }
}

__global__ void __launch_bounds__(256) scatter_kernel(
    const float* __restrict__ vals, const int* __restrict__ row,
    const int* __restrict__ col, int nedges)
{
    int i = blockIdx.x * blockDim.x + threadIdx.x;
    int stride = gridDim.x * blockDim.x;
    for (; i < nedges; i += stride) {
        int r = row[i];
        int p = atomicAdd(&g_cursor[r], 1);
        g_perm[p] = make_int2(col[i], __float_as_int(vals[i]));
    }
}

// ---------------------------------------------------------------------------
// Warp-per-node aggregation + fused relu, fp16 gather, 4-edge unroll.
// ---------------------------------------------------------------------------
__global__ void __launch_bounds__(256) gin_agg_kernel(float* __restrict__ out, int nnodes)
{
    const int node = (blockIdx.x * blockDim.x + threadIdx.x) >> 5;
    if (node >= nnodes) return;
    const int lane = threadIdx.x & 31;

    const int s   = g_starts[node];
    const int end = s + g_counts[node];

    float4 acc[4];
#pragma unroll
    for (int j = 0; j < 4; j++) acc[j] = make_float4(0.f, 0.f, 0.f, 0.f);

    int e = s;
    for (; e + 4 <= end; e += 4) {
        int2 p[4];
#pragma unroll
        for (int j = 0; j < 4; j++) p[j] = g_perm[e + j];
        uint2 raw[4];
#pragma unroll
        for (int j = 0; j < 4; j++)
            raw[j] = *(const uint2*)&g_h16[(size_t)p[j].x * (UNITS / 2) + lane * 2];
#pragma unroll
        for (int j = 0; j < 4; j++) {
            float v = __int_as_float(p[j].y);
            float2 fa = unpack_h2(raw[j].x);
            float2 fb = unpack_h2(raw[j].y);
            acc[j].x = fmaf(v, fa.x, acc[j].x);
            acc[j].y = fmaf(v, fa.y, acc[j].y);
            acc[j].z = fmaf(v, fb.x, acc[j].z);
            acc[j].w = fmaf(v, fb.y, acc[j].w);
        }
    }
    for (; e < end; e++) {
        int2 p = g_perm[e];
        uint2 raw = *(const uint2*)&g_h16[(size_t)p.x * (UNITS / 2) + lane * 2];
        float v = __int_as_float(p.y);
        float2 fa = unpack_h2(raw.x);
        float2 fb = unpack_h2(raw.y);
        acc[0].x = fmaf(v, fa.x, acc[0].x);
        acc[0].y = fmaf(v, fa.y, acc[0].y);
        acc[0].z = fmaf(v, fb.x, acc[0].z);
        acc[0].w = fmaf(v, fb.y, acc[0].w);
    }

    float* dst = out + (size_t)node * UNITS + lane * 4;
    float4 o = *(float4*)dst;
    o.x = fmaxf(o.x + acc[0].x + acc[1].x + acc[2].x + acc[3].x, 0.f);
    o.y = fmaxf(o.y + acc[0].y + acc[1].y + acc[2].y + acc[3].y, 0.f);
    o.z = fmaxf(o.z + acc[0].z + acc[1].z + acc[2].z + acc[3].z, 0.f);
    o.w = fmaxf(o.w + acc[0].w + acc[1].w + acc[2].w + acc[3].w, 0.f);
    *(float4*)dst = o;
}

// ---------------------------------------------------------------------------
extern "C" void kernel_launch(void* const* d_in, const int* in_sizes, int n_in,
                              void* d_out, int out_size)
{
    const float* x    = (const float*)d_in[0];
    const float* W    = (const float*)d_in[1];
    const float* bias = (const float*)d_in[2];
    const float* eps  = (const float*)d_in[3];
    const float* vals = (const float*)d_in[4];
    const int*   row  = (const int*)d_in[5];
    const int*   col  = (const int*)d_in[6];
    float* out = (float*)d_out;

    const int nnodes = in_sizes[0] / UNITS;
    const int nedges = in_sizes[4];

    // 1. GEMM + base epilogue (writes g_h16 and out base)
    int gemm_blocks = (nnodes + 127) / 128;
    gin_gemm_kernel<<<gemm_blocks, 256>>>(x, W, bias, eps, out, nnodes);

    // 2. counting sort of edges by row
    int nscan = (nnodes + 255) / 256;
    zero_counts_kernel<<<nscan, 256>>>(nnodes);
    hist_kernel<<<1024, 256>>>(row, nedges);
    scan_block_kernel<<<nscan, 256>>>(nnodes);
    scan_sums_kernel<<<1, 512>>>(nscan);
    finalize_starts_kernel<<<nscan, 256>>>(nnodes);
    scatter_kernel<<<1024, 256>>>(vals, row, col, nedges);

    // 3. warp-per-node aggregation + fused relu (fp16 gather)
    int agg_blocks = (nnodes + 7) / 8;
    gin_agg_kernel<<<agg_blocks, 256>>>(out, nnodes);
}

// round 7
// speedup vs baseline: 1.9008x; 1.1521x over previous
#include <cuda_runtime.h>
#include <cuda_fp16.h>
#include <cuda_bf16.h>

#define UNITS 128
#define MAX_NODES 100000
#define MAX_EDGES 1600000

// ------------------------- static scratch (no allocs) -----------------------
__device__ unsigned g_h16[(size_t)MAX_NODES * (UNITS / 2)];  // fp16 h
__device__ int2  g_perm[MAX_EDGES];
__device__ int   g_counts[MAX_NODES];
__device__ int   g_starts[MAX_NODES];
__device__ int   g_cursor[MAX_NODES];
__device__ int   g_bsums[512];
// W transposed + bf16 split, plain [n][k] row-major, packed 2 bf16 per u32
__device__ unsigned g_Bhi[8192];   // Bt_hi[n][k]
__device__ unsigned g_Blo[8192];   // Bt_lo[n][k]

// ------------------------- helpers ------------------------------------------
__device__ __forceinline__ unsigned pack_h2(float a, float b) {
    unsigned r;
    asm("cvt.rn.f16x2.f32 %0, %1, %2;" : "=r"(r) : "f"(b), "f"(a));
    return r;
}
__device__ __forceinline__ float2 unpack_h2(unsigned u) {
    __half2 h = *(__half2*)&u;
    return __half22float2(h);
}
__device__ __forceinline__ unsigned short bf16bits(float f) {
    __nv_bfloat16 h = __float2bfloat16(f);
    return *(unsigned short*)&h;
}
__device__ __forceinline__ float bf16val(float f) {
    return __bfloat162float(__float2bfloat16(f));
}
__device__ __forceinline__ unsigned smem_u32(const void* p) {
    unsigned a;
    asm("{ .reg .u64 t; cvta.to.shared.u64 t, %1; cvt.u32.u64 %0, t; }" : "=r"(a) : "l"(p));
    return a;
}
__device__ __forceinline__ void ldsm_x4(unsigned& r0, unsigned& r1,
                                        unsigned& r2, unsigned& r3, unsigned addr) {
    asm volatile("ldmatrix.sync.aligned.m8n8.x4.shared.b16 {%0,%1,%2,%3}, [%4];"
                 : "=r"(r0), "=r"(r1), "=r"(r2), "=r"(r3) : "r"(addr));
}
__device__ __forceinline__ void mma_bf16(float* c, const unsigned* a,
                                         unsigned b0, unsigned b1) {
    asm volatile(
        "mma.sync.aligned.m16n8k16.row.col.f32.bf16.bf16.f32 "
        "{%0,%1,%2,%3}, {%4,%5,%6,%7}, {%8,%9}, {%0,%1,%2,%3};"
        : "+f"(c[0]), "+f"(c[1]), "+f"(c[2]), "+f"(c[3])
        : "r"(a[0]), "r"(a[1]), "r"(a[2]), "r"(a[3]), "r"(b0), "r"(b1));
}

// ---------------------------------------------------------------------------
// W prep: g_B{hi,lo}[n*64 + k/2] = bf16 split of W[k][n] (Bt row-major [n][k])
// ---------------------------------------------------------------------------
__global__ void __launch_bounds__(256) prep_w_kernel(const float* __restrict__ W)
{
    int idx = blockIdx.x * blockDim.x + threadIdx.x;   // 8192 items
    if (idx >= 8192) return;
    int n = idx >> 6;
    int j = idx & 63;
    int k = 2 * j;
    float w0 = W[(size_t)k * UNITS + n];
    float w1 = W[(size_t)(k + 1) * UNITS + n];
    unsigned hi = (unsigned)bf16bits(w0) | ((unsigned)bf16bits(w1) << 16);
    unsigned lo = (unsigned)bf16bits(w0 - bf16val(w0)) |
                  ((unsigned)bf16bits(w1 - bf16val(w1)) << 16);
    g_Bhi[idx] = hi;
    g_Blo[idx] = lo;
}

// ---------------------------------------------------------------------------
// mma.sync bf16 GEMM: h = x @ W (3-term split), epilogue writes g_h16 (fp16)
// and out_base = (1+eps)*h + bias (fp32).
// Block: 128 rows x 128 cols, 256 threads (8 warps, warp tile 64x32).
// SMEM rows padded to 272B -> conflict-free ldmatrix.
// ---------------------------------------------------------------------------
#define ROWB 272
#define TILEB (128 * ROWB)             // 34816 per buffer
#define SMT (4 * TILEB)                // A_hi, A_lo, B_hi, B_lo

__global__ void __launch_bounds__(256) gin_gemm_mma_kernel(
    const float* __restrict__ x, const float* __restrict__ bias,
    const float* __restrict__ eps, float* __restrict__ out_base, int nrows)
{
    extern __shared__ __align__(128) char smem[];
    const unsigned sbase = smem_u32(smem);
    const unsigned sAhi = sbase;
    const unsigned sAlo = sbase + TILEB;
    const unsigned sBhi = sbase + 2 * TILEB;
    const unsigned sBlo = sbase + 3 * TILEB;

    const int tid = threadIdx.x;
    const int wid = tid >> 5;
    const int lane = tid & 31;
    const int row0 = blockIdx.x * 128;

    // ---- copy Bt splits into padded smem (coalesced uint4) ----
    // 128 rows x 256 bytes = 16 uint4 per row, 2048 uint4 per buffer
    {
        const uint4* gh = (const uint4*)g_Bhi;
        const uint4* gl = (const uint4*)g_Blo;
#pragma unroll
        for (int i = 0; i < 8; i++) {
            int j = tid + i * 256;           // uint4 index, 2048 total
            int n = j >> 4, c16 = j & 15;    // 16 uint4 per 128-bf16 row
            unsigned dst = n * ROWB + c16 * 16;
            *(uint4*)(smem + 2 * TILEB + dst) = gh[j];
            *(uint4*)(smem + 3 * TILEB + dst) = gl[j];
        }
    }

    // ---- load x, split into bf16 hi/lo, store padded rows ----
#pragma unroll
    for (int it = 0; it < 16; it++) {
        int idx = tid + it * 256;
        int r = idx >> 5;          // row in tile
        int q = idx & 31;          // float4 group -> cols 4q..4q+3
        int gr = row0 + r;
        float4 v = make_float4(0.f, 0.f, 0.f, 0.f);
        if (gr < nrows) v = *(const float4*)&x[(size_t)gr * UNITS + q * 4];
        unsigned h01 = (unsigned)bf16bits(v.x) | ((unsigned)bf16bits(v.y) << 16);
        unsigned h23 = (unsigned)bf16bits(v.z) | ((unsigned)bf16bits(v.w) << 16);
        unsigned l01 = (unsigned)bf16bits(v.x - bf16val(v.x)) |
                       ((unsigned)bf16bits(v.y - bf16val(v.y)) << 16);
        unsigned l23 = (unsigned)bf16bits(v.z - bf16val(v.z)) |
                       ((unsigned)bf16bits(v.w - bf16val(v.w)) << 16);
        unsigned dst = r * ROWB + q * 8;
        *(uint2*)(smem + dst) = make_uint2(h01, h23);                    // A_hi
        *(uint2*)(smem + TILEB + dst) = make_uint2(l01, l23);            // A_lo
    }
    __syncthreads();

    // ---- warp tiles: wm = (wid>>2)*64, wn = (wid&3)*32 ----
    const int wm = (wid >> 2) * 64;
    const int wn = (wid & 3) * 32;
    const int msub = lane >> 3;    // 0..3
    const int mr   = lane & 7;     // 0..7

    float acc[4][4][4];            // [mi][ni][c]
#pragma unroll
    for (int mi = 0; mi < 4; mi++)
#pragma unroll
        for (int ni = 0; ni < 4; ni++)
#pragma unroll
            for (int c = 0; c < 4; c++) acc[mi][ni][c] = 0.f;

    // term list: (A,B) = (hi,hi), (hi,lo), (lo,hi)
#pragma unroll
    for (int term = 0; term < 3; term++) {
        const unsigned Asrc = (term == 2) ? sAlo : sAhi;
        const unsigned Bsrc = (term == 1) ? sBlo : sBhi;
#pragma unroll
        for (int ks = 0; ks < 8; ks++) {
            const int k0 = ks * 16;
            // A fragments: 4 m-tiles
            unsigned a[4][4];
#pragma unroll
            for (int mi = 0; mi < 4; mi++) {
                int arow = wm + mi * 16 + (msub & 1) * 8 + mr;
                int acolb = (k0 + (msub >> 1) * 8) * 2;
                ldsm_x4(a[mi][0], a[mi][1], a[mi][2], a[mi][3],
                        Asrc + arow * ROWB + acolb);
            }
            // B fragments: 2 n-tile pairs (each x4 covers two n8 tiles)
            unsigned b[2][4];
#pragma unroll
            for (int nb = 0; nb < 2; nb++) {
                int brow = wn + nb * 16 + (msub >> 1) * 8 + mr;
                int bcolb = (k0 + (msub & 1) * 8) * 2;
                ldsm_x4(b[nb][0], b[nb][1], b[nb][2], b[nb][3],
                        Bsrc + brow * ROWB + bcolb);
            }
#pragma unroll
            for (int mi = 0; mi < 4; mi++)
#pragma unroll
                for (int ni = 0; ni < 4; ni++)
                    mma_bf16(acc[mi][ni], a[mi],
                             b[ni >> 1][(ni & 1) * 2], b[ni >> 1][(ni & 1) * 2 + 1]);
        }
    }

    // ---- epilogue ----
    const float e1 = 1.0f + eps[0];
    const int g   = lane >> 2;
    const int tig = lane & 3;
#pragma unroll
    for (int mi = 0; mi < 4; mi++) {
#pragma unroll
        for (int half = 0; half < 2; half++) {
            int gr = row0 + wm + mi * 16 + g + half * 8;
            if (gr >= nrows) continue;
#pragma unroll
            for (int ni = 0; ni < 4; ni++) {
                int col = wn + ni * 8 + tig * 2;
                float c0 = acc[mi][ni][half * 2];
                float c1 = acc[mi][ni][half * 2 + 1];
                // fp16 copy of h
                g_h16[(size_t)gr * 64 + (col >> 1)] = pack_h2(c0, c1);
                // fp32 base
                float2 bv = *(const float2*)&bias[col];
                float2 o;
                o.x = fmaf(e1, c0, bv.x);
                o.y = fmaf(e1, c1, bv.y);
                *(float2*)&out_base[(size_t)gr * UNITS + col] = o;
            }
        }
    }
}

// ---------------------------------------------------------------------------
// Counting sort of edges by destination row
// ---------------------------------------------------------------------------
__global__ void __launch_bounds__(256) zero_counts_kernel(int n)
{
    int i = blockIdx.x * blockDim.x + threadIdx.x;
    int stride = gridDim.x * blockDim.x;
    for (; i < n; i += stride) g_counts[i] = 0;
}

__global__ void __launch_bounds__(256) hist_kernel(const int* __restrict__ row, int nedges)
{
    int i = blockIdx.x * blockDim.x + threadIdx.x;
    int stride = gridDim.x * blockDim.x;
    for (; i < nedges; i += stride) atomicAdd(&g_counts[row[i]], 1);
}

__global__ void __launch_bounds__(256) scan_block_kernel(int n)
{
    __shared__ int sh[256];
    int i = blockIdx.x * 256 + threadIdx.x;
    int v = (i < n) ? g_counts[i] : 0;
    sh[threadIdx.x] = v;
    __syncthreads();
#pragma unroll
    for (int off = 1; off < 256; off <<= 1) {
        int t = (threadIdx.x >= off) ? sh[threadIdx.x - off] : 0;
        __syncthreads();
        sh[threadIdx.x] += t;
        __syncthreads();
    }
    if (i < n) g_starts[i] = sh[threadIdx.x] - v;
    if (threadIdx.x == 255) g_bsums[blockIdx.x] = sh[255];
}

__global__ void __launch_bounds__(512) scan_sums_kernel(int nb)
{
    __shared__ int sh[512];
    int t = threadIdx.x;
    int v = (t < nb) ? g_bsums[t] : 0;
    sh[t] = v;
    __syncthreads();
#pragma unroll
    for (int off = 1; off < 512; off <<= 1) {
        int u = (t >= off) ? sh[t - off] : 0;
        __syncthreads();
        sh[t] += u;
        __syncthreads();
    }
    if (t < nb) g_bsums[t] = sh[t] - v;
}

__global__ void __launch_bounds__(256) finalize_starts_kernel(int n)
{
    int i = blockIdx.x * blockDim.x + threadIdx.x;
    if (i < n) {
        int s = g_starts[i] + g_bsums[i >> 8];
        g_starts[i] = s;
        g_cursor[i] = s;
    }
}

__global__ void __launch_bounds__(256) scatter_kernel(
    const float* __restrict__ vals, const int* __restrict__ row,
    const int* __restrict__ col, int nedges)
{
    int i = blockIdx.x * blockDim.x + threadIdx.x;
    int stride = gridDim.x * blockDim.x;
    for (; i < nedges; i += stride) {
        int r = row[i];
        int p = atomicAdd(&g_cursor[r], 1);
        g_perm[p] = make_int2(col[i], __float_as_int(vals[i]));
    }
}

// ---------------------------------------------------------------------------
// Warp-per-node aggregation + fused relu (fp16 gather, 4-edge unroll)
// ---------------------------------------------------------------------------
__global__ void __launch_bounds__(256) gin_agg_kernel(float* __restrict__ out, int nnodes)
{
    const int node = (blockIdx.x * blockDim.x + threadIdx.x) >> 5;
    if (node >= nnodes) return;
    const int lane = threadIdx.x & 31;

    const int s   = g_starts[node];
    const int end = s + g_counts[node];

    float4 acc[4];
#pragma unroll
    for (int j = 0; j < 4; j++) acc[j] = make_float4(0.f, 0.f, 0.f, 0.f);

    int e = s;
    for (; e + 4 <= end; e += 4) {
        int2 p[4];
#pragma unroll
        for (int j = 0; j < 4; j++) p[j] = g_perm[e + j];
        uint2 raw[4];
#pragma unroll
        for (int j = 0; j < 4; j++)
            raw[j] = *(const uint2*)&g_h16[(size_t)p[j].x * (UNITS / 2) + lane * 2];
#pragma unroll
        for (int j = 0; j < 4; j++) {
            float v = __int_as_float(p[j].y);
            float2 fa = unpack_h2(raw[j].x);
            float2 fb = unpack_h2(raw[j].y);
            acc[j].x = fmaf(v, fa.x, acc[j].x);
            acc[j].y = fmaf(v, fa.y, acc[j].y);
            acc[j].z = fmaf(v, fb.x, acc[j].z);
            acc[j].w = fmaf(v, fb.y, acc[j].w);
        }
    }
    for (; e < end; e++) {
        int2 p = g_perm[e];
        uint2 raw = *(const uint2*)&g_h16[(size_t)p.x * (UNITS / 2) + lane * 2];
        float v = __int_as_float(p.y);
        float2 fa = unpack_h2(raw.x);
        float2 fb = unpack_h2(raw.y);
        acc[0].x = fmaf(v, fa.x, acc[0].x);
        acc[0].y = fmaf(v, fa.y, acc[0].y);
        acc[0].z = fmaf(v, fb.x, acc[0].z);
        acc[0].w = fmaf(v, fb.y, acc[0].w);
    }

    float* dst = out + (size_t)node * UNITS + lane * 4;
    float4 o = *(float4*)dst;
    o.x = fmaxf(o.x + acc[0].x + acc[1].x + acc[2].x + acc[3].x, 0.f);
    o.y = fmaxf(o.y + acc[0].y + acc[1].y + acc[2].y + acc[3].y, 0.f);
    o.z = fmaxf(o.z + acc[0].z + acc[1].z + acc[2].z + acc[3].z, 0.f);
    o.w = fmaxf(o.w + acc[0].w + acc[1].w + acc[2].w + acc[3].w, 0.f);
    *(float4*)dst = o;
}

// ---------------------------------------------------------------------------
extern "C" void kernel_launch(void* const* d_in, const int* in_sizes, int n_in,
                              void* d_out, int out_size)
{
    const float* x    = (const float*)d_in[0];
    const float* W    = (const float*)d_in[1];
    const float* bias = (const float*)d_in[2];
    const float* eps  = (const float*)d_in[3];
    const float* vals = (const float*)d_in[4];
    const int*   row  = (const int*)d_in[5];
    const int*   col  = (const int*)d_in[6];
    float* out = (float*)d_out;

    const int nnodes = in_sizes[0] / UNITS;
    const int nedges = in_sizes[4];

    cudaFuncSetAttribute(gin_gemm_mma_kernel,
                         cudaFuncAttributeMaxDynamicSharedMemorySize, SMT);

    // 0. W transpose + bf16 split (once per call, tiny)
    prep_w_kernel<<<32, 256>>>(W);

    // 1. mma.sync GEMM + epilogue (writes g_h16 and out base)
    int gemm_blocks = (nnodes + 127) / 128;
    gin_gemm_mma_kernel<<<gemm_blocks, 256, SMT>>>(x, bias, eps, out, nnodes);

    // 2. counting sort of edges by row
    int nscan = (nnodes + 255) / 256;
    zero_counts_kernel<<<nscan, 256>>>(nnodes);
    hist_kernel<<<1024, 256>>>(row, nedges);
    scan_block_kernel<<<nscan, 256>>>(nnodes);
    scan_sums_kernel<<<1, 512>>>(nscan);
    finalize_starts_kernel<<<nscan, 256>>>(nnodes);
    scatter_kernel<<<1024, 256>>>(vals, row, col, nedges);

    // 3. warp-per-node aggregation + fused relu
    int agg_blocks = (nnodes + 7) / 8;
    gin_agg_kernel<<<agg_blocks, 256>>>(out, nnodes);
}

// round 8
// speedup vs baseline: 1.9656x; 1.0341x over previous
#include <cuda_runtime.h>
#include <cuda_fp16.h>
#include <cuda_bf16.h>

#define UNITS 128
#define MAX_NODES 100000
#define MAX_EDGES 1600000

// ------------------------- static scratch (no allocs) -----------------------
__device__ unsigned g_h16[(size_t)MAX_NODES * (UNITS / 2)];  // fp16 h
__device__ int2  g_perm[MAX_EDGES];
__device__ int   g_counts[MAX_NODES];
__device__ int   g_starts[MAX_NODES];
__device__ int   g_cursor[MAX_NODES];
__device__ int   g_bsums[512];
// W transposed + bf16 split, plain [n][k] row-major, packed 2 bf16 per u32
__device__ unsigned g_Bhi[8192];   // Bt_hi[n][k]
__device__ unsigned g_Blo[8192];   // Bt_lo[n][k]

// ------------------------- helpers ------------------------------------------
__device__ __forceinline__ unsigned pack_h2(float a, float b) {
    unsigned r;
    asm("cvt.rn.f16x2.f32 %0, %1, %2;" : "=r"(r) : "f"(b), "f"(a));
    return r;
}
__device__ __forceinline__ float2 unpack_h2(unsigned u) {
    __half2 h = *(__half2*)&u;
    return __half22float2(h);
}
__device__ __forceinline__ unsigned short bf16bits(float f) {
    __nv_bfloat16 h = __float2bfloat16(f);
    return *(unsigned short*)&h;
}
__device__ __forceinline__ float bf16val(float f) {
    return __bfloat162float(__float2bfloat16(f));
}
__device__ __forceinline__ unsigned smem_u32(const void* p) {
    unsigned a;
    asm("{ .reg .u64 t; cvta.to.shared.u64 t, %1; cvt.u32.u64 %0, t; }" : "=r"(a) : "l"(p));
    return a;
}
__device__ __forceinline__ void ldsm_x4(unsigned& r0, unsigned& r1,
                                        unsigned& r2, unsigned& r3, unsigned addr) {
    asm volatile("ldmatrix.sync.aligned.m8n8.x4.shared.b16 {%0,%1,%2,%3}, [%4];"
                 : "=r"(r0), "=r"(r1), "=r"(r2), "=r"(r3) : "r"(addr));
}
__device__ __forceinline__ void mma_bf16(float* c, const unsigned* a,
                                         unsigned b0, unsigned b1) {
    asm volatile(
        "mma.sync.aligned.m16n8k16.row.col.f32.bf16.bf16.f32 "
        "{%0,%1,%2,%3}, {%4,%5,%6,%7}, {%8,%9}, {%0,%1,%2,%3};"
        : "+f"(c[0]), "+f"(c[1]), "+f"(c[2]), "+f"(c[3])
        : "r"(a[0]), "r"(a[1]), "r"(a[2]), "r"(a[3]), "r"(b0), "r"(b1));
}

// ---------------------------------------------------------------------------
// W prep: g_B{hi,lo}[n*64 + k/2] = bf16 split of W[k][n] (Bt row-major [n][k])
// ---------------------------------------------------------------------------
__global__ void __launch_bounds__(256) prep_w_kernel(const float* __restrict__ W)
{
    int idx = blockIdx.x * blockDim.x + threadIdx.x;   // 8192 items
    if (idx >= 8192) return;
    int n = idx >> 6;
    int j = idx & 63;
    int k = 2 * j;
    float w0 = W[(size_t)k * UNITS + n];
    float w1 = W[(size_t)(k + 1) * UNITS + n];
    unsigned hi = (unsigned)bf16bits(w0) | ((unsigned)bf16bits(w1) << 16);
    unsigned lo = (unsigned)bf16bits(w0 - bf16val(w0)) |
                  ((unsigned)bf16bits(w1 - bf16val(w1)) << 16);
    g_Bhi[idx] = hi;
    g_Blo[idx] = lo;
}

// ---------------------------------------------------------------------------
// mma.sync bf16 GEMM: h = x @ W (3-term split), epilogue writes g_h16 (fp16)
// and out_base = (1+eps)*h + bias (fp32).
// ---------------------------------------------------------------------------
#define ROWB 272
#define TILEB (128 * ROWB)             // 34816 per buffer
#define SMT (4 * TILEB)                // A_hi, A_lo, B_hi, B_lo

__global__ void __launch_bounds__(256) gin_gemm_mma_kernel(
    const float* __restrict__ x, const float* __restrict__ bias,
    const float* __restrict__ eps, float* __restrict__ out_base, int nrows)
{
    extern __shared__ __align__(128) char smem[];
    const unsigned sbase = smem_u32(smem);
    const unsigned sAhi = sbase;
    const unsigned sAlo = sbase + TILEB;
    const unsigned sBhi = sbase + 2 * TILEB;
    const unsigned sBlo = sbase + 3 * TILEB;

    const int tid = threadIdx.x;
    const int wid = tid >> 5;
    const int lane = tid & 31;
    const int row0 = blockIdx.x * 128;

    // ---- copy Bt splits into padded smem: 16 uint4 per row, 2048 total ----
    {
        const uint4* gh = (const uint4*)g_Bhi;
        const uint4* gl = (const uint4*)g_Blo;
#pragma unroll
        for (int i = 0; i < 8; i++) {
            int j = tid + i * 256;
            int n = j >> 4, c16 = j & 15;
            unsigned dst = n * ROWB + c16 * 16;
            *(uint4*)(smem + 2 * TILEB + dst) = gh[j];
            *(uint4*)(smem + 3 * TILEB + dst) = gl[j];
        }
    }

    // ---- load x, split into bf16 hi/lo, store padded rows ----
#pragma unroll
    for (int it = 0; it < 16; it++) {
        int idx = tid + it * 256;
        int r = idx >> 5;
        int q = idx & 31;
        int gr = row0 + r;
        float4 v = make_float4(0.f, 0.f, 0.f, 0.f);
        if (gr < nrows) v = *(const float4*)&x[(size_t)gr * UNITS + q * 4];
        unsigned h01 = (unsigned)bf16bits(v.x) | ((unsigned)bf16bits(v.y) << 16);
        unsigned h23 = (unsigned)bf16bits(v.z) | ((unsigned)bf16bits(v.w) << 16);
        unsigned l01 = (unsigned)bf16bits(v.x - bf16val(v.x)) |
                       ((unsigned)bf16bits(v.y - bf16val(v.y)) << 16);
        unsigned l23 = (unsigned)bf16bits(v.z - bf16val(v.z)) |
                       ((unsigned)bf16bits(v.w - bf16val(v.w)) << 16);
        unsigned dst = r * ROWB + q * 8;
        *(uint2*)(smem + dst) = make_uint2(h01, h23);                    // A_hi
        *(uint2*)(smem + TILEB + dst) = make_uint2(l01, l23);            // A_lo
    }
    __syncthreads();

    const int wm = (wid >> 2) * 64;
    const int wn = (wid & 3) * 32;
    const int msub = lane >> 3;
    const int mr   = lane & 7;

    float acc[4][4][4];
#pragma unroll
    for (int mi = 0; mi < 4; mi++)
#pragma unroll
        for (int ni = 0; ni < 4; ni++)
#pragma unroll
            for (int c = 0; c < 4; c++) acc[mi][ni][c] = 0.f;

#pragma unroll
    for (int term = 0; term < 3; term++) {
        const unsigned Asrc = (term == 2) ? sAlo : sAhi;
        const unsigned Bsrc = (term == 1) ? sBlo : sBhi;
#pragma unroll
        for (int ks = 0; ks < 8; ks++) {
            const int k0 = ks * 16;
            unsigned a[4][4];
#pragma unroll
            for (int mi = 0; mi < 4; mi++) {
                int arow = wm + mi * 16 + (msub & 1) * 8 + mr;
                int acolb = (k0 + (msub >> 1) * 8) * 2;
                ldsm_x4(a[mi][0], a[mi][1], a[mi][2], a[mi][3],
                        Asrc + arow * ROWB + acolb);
            }
            unsigned b[2][4];
#pragma unroll
            for (int nb = 0; nb < 2; nb++) {
                int brow = wn + nb * 16 + (msub >> 1) * 8 + mr;
                int bcolb = (k0 + (msub & 1) * 8) * 2;
                ldsm_x4(b[nb][0], b[nb][1], b[nb][2], b[nb][3],
                        Bsrc + brow * ROWB + bcolb);
            }
#pragma unroll
            for (int mi = 0; mi < 4; mi++)
#pragma unroll
                for (int ni = 0; ni < 4; ni++)
                    mma_bf16(acc[mi][ni], a[mi],
                             b[ni >> 1][(ni & 1) * 2], b[ni >> 1][(ni & 1) * 2 + 1]);
        }
    }

    // ---- epilogue ----
    const float e1 = 1.0f + eps[0];
    const int g   = lane >> 2;
    const int tig = lane & 3;
#pragma unroll
    for (int mi = 0; mi < 4; mi++) {
#pragma unroll
        for (int half = 0; half < 2; half++) {
            int gr = row0 + wm + mi * 16 + g + half * 8;
            if (gr >= nrows) continue;
#pragma unroll
            for (int ni = 0; ni < 4; ni++) {
                int col = wn + ni * 8 + tig * 2;
                float c0 = acc[mi][ni][half * 2];
                float c1 = acc[mi][ni][half * 2 + 1];
                g_h16[(size_t)gr * 64 + (col >> 1)] = pack_h2(c0, c1);
                float2 bv = *(const float2*)&bias[col];
                float2 o;
                o.x = fmaf(e1, c0, bv.x);
                o.y = fmaf(e1, c1, bv.y);
                *(float2*)&out_base[(size_t)gr * UNITS + col] = o;
            }
        }
    }
}

// ---------------------------------------------------------------------------
// Counting sort of edges by destination row
// ---------------------------------------------------------------------------
__global__ void __launch_bounds__(256) zero_counts_kernel(int n)
{
    int i = blockIdx.x * blockDim.x + threadIdx.x;
    int stride = gridDim.x * blockDim.x;
    for (; i < n; i += stride) g_counts[i] = 0;
}

__global__ void __launch_bounds__(256) hist_kernel(const int* __restrict__ row, int nedges)
{
    int i = blockIdx.x * blockDim.x + threadIdx.x;
    int stride = gridDim.x * blockDim.x;
    for (; i < nedges; i += stride) atomicAdd(&g_counts[row[i]], 1);
}

__global__ void __launch_bounds__(256) scan_block_kernel(int n)
{
    __shared__ int sh[256];
    int i = blockIdx.x * 256 + threadIdx.x;
    int v = (i < n) ? g_counts[i] : 0;
    sh[threadIdx.x] = v;
    __syncthreads();
#pragma unroll
    for (int off = 1; off < 256; off <<= 1) {
        int t = (threadIdx.x >= off) ? sh[threadIdx.x - off] : 0;
        __syncthreads();
        sh[threadIdx.x] += t;
        __syncthreads();
    }
    if (i < n) g_starts[i] = sh[threadIdx.x] - v;
    if (threadIdx.x == 255) g_bsums[blockIdx.x] = sh[255];
}

__global__ void __launch_bounds__(512) scan_sums_kernel(int nb)
{
    __shared__ int sh[512];
    int t = threadIdx.x;
    int v = (t < nb) ? g_bsums[t] : 0;
    sh[t] = v;
    __syncthreads();
#pragma unroll
    for (int off = 1; off < 512; off <<= 1) {
        int u = (t >= off) ? sh[t - off] : 0;
        __syncthreads();
        sh[t] += u;
        __syncthreads();
    }
    if (t < nb) g_bsums[t] = sh[t] - v;
}

__global__ void __launch_bounds__(256) finalize_starts_kernel(int n)
{
    int i = blockIdx.x * blockDim.x + threadIdx.x;
    if (i < n) {
        int s = g_starts[i] + g_bsums[i >> 8];
        g_starts[i] = s;
        g_cursor[i] = s;
    }
}

__global__ void __launch_bounds__(256) scatter_kernel(
    const float* __restrict__ vals, const int* __restrict__ row,
    const int* __restrict__ col, int nedges)
{
    int i = blockIdx.x * blockDim.x + threadIdx.x;
    int stride = gridDim.x * blockDim.x;
    for (; i < nedges; i += stride) {
        int r = row[i];
        int p = atomicAdd(&g_cursor[r], 1);
        g_perm[p] = make_int2(col[i], __float_as_int(vals[i]));
    }
}

// ---------------------------------------------------------------------------
// Warp-per-node aggregation + fused relu (fp16 gather, 8-edge unroll)
// ---------------------------------------------------------------------------
__global__ void __launch_bounds__(256) gin_agg_kernel(float* __restrict__ out, int nnodes)
{
    const int node = (blockIdx.x * blockDim.x + threadIdx.x) >> 5;
    if (node >= nnodes) return;
    const int lane = threadIdx.x & 31;

    const int s   = g_starts[node];
    const int end = s + g_counts[node];

    float4 acc[4];
#pragma unroll
    for (int j = 0; j < 4; j++) acc[j] = make_float4(0.f, 0.f, 0.f, 0.f);

    int e = s;
    // 8-edge batches: 8 independent gathers in flight per lane
    for (; e + 8 <= end; e += 8) {
        int2 p[8];
#pragma unroll
        for (int j = 0; j < 8; j++) p[j] = g_perm[e + j];
        uint2 raw[8];
#pragma unroll
        for (int j = 0; j < 8; j++)
            raw[j] = *(const uint2*)&g_h16[(size_t)p[j].x * (UNITS / 2) + lane * 2];
#pragma unroll
        for (int j = 0; j < 8; j++) {
            float v = __int_as_float(p[j].y);
            float2 fa = unpack_h2(raw[j].x);
            float2 fb = unpack_h2(raw[j].y);
            acc[j & 3].x = fmaf(v, fa.x, acc[j & 3].x);
            acc[j & 3].y = fmaf(v, fa.y, acc[j & 3].y);
            acc[j & 3].z = fmaf(v, fb.x, acc[j & 3].z);
            acc[j & 3].w = fmaf(v, fb.y, acc[j & 3].w);
        }
    }
    for (; e + 4 <= end; e += 4) {
        int2 p[4];
#pragma unroll
        for (int j = 0; j < 4; j++) p[j] = g_perm[e + j];
        uint2 raw[4];
#pragma unroll
        for (int j = 0; j < 4; j++)
            raw[j] = *(const uint2*)&g_h16[(size_t)p[j].x * (UNITS / 2) + lane * 2];
#pragma unroll
        for (int j = 0; j < 4; j++) {
            float v = __int_as_float(p[j].y);
            float2 fa = unpack_h2(raw[j].x);
            float2 fb = unpack_h2(raw[j].y);
            acc[j].x = fmaf(v, fa.x, acc[j].x);
            acc[j].y = fmaf(v, fa.y, acc[j].y);
            acc[j].z = fmaf(v, fb.x, acc[j].z);
            acc[j].w = fmaf(v, fb.y, acc[j].w);
        }
    }
    for (; e < end; e++) {
        int2 p = g_perm[e];
        uint2 raw = *(const uint2*)&g_h16[(size_t)p.x * (UNITS / 2) + lane * 2];
        float v = __int_as_float(p.y);
        float2 fa = unpack_h2(raw.x);
        float2 fb = unpack_h2(raw.y);
        acc[0].x = fmaf(v, fa.x, acc[0].x);
        acc[0].y = fmaf(v, fa.y, acc[0].y);
        acc[0].z = fmaf(v, fb.x, acc[0].z);
        acc[0].w = fmaf(v, fb.y, acc[0].w);
    }

    float* dst = out + (size_t)node * UNITS + lane * 4;
    float4 o = *(float4*)dst;
    o.x = fmaxf(o.x + acc[0].x + acc[1].x + acc[2].x + acc[3].x, 0.f);
    o.y = fmaxf(o.y + acc[0].y + acc[1].y + acc[2].y + acc[3].y, 0.f);
    o.z = fmaxf(o.z + acc[0].z + acc[1].z + acc[2].z + acc[3].z, 0.f);
    o.w = fmaxf(o.w + acc[0].w + acc[1].w + acc[2].w + acc[3].w, 0.f);
    *(float4*)dst = o;
}

// ---------------------------------------------------------------------------
extern "C" void kernel_launch(void* const* d_in, const int* in_sizes, int n_in,
                              void* d_out, int out_size)
{
    const float* x    = (const float*)d_in[0];
    const float* W    = (const float*)d_in[1];
    const float* bias = (const float*)d_in[2];
    const float* eps  = (const float*)d_in[3];
    const float* vals = (const float*)d_in[4];
    const int*   row  = (const int*)d_in[5];
    const int*   col  = (const int*)d_in[6];
    float* out = (float*)d_out;

    const int nnodes = in_sizes[0] / UNITS;
    const int nedges = in_sizes[4];

    // Lazily-created side stream + fork/join events (host objects; no device
    // memory). Work is identical on every call.
    static cudaStream_t s2 = nullptr;
    static cudaEvent_t evFork = nullptr, evJoin = nullptr;
    if (s2 == nullptr) {
        cudaStreamCreateWithFlags(&s2, cudaStreamNonBlocking);
        cudaEventCreateWithFlags(&evFork, cudaEventDisableTiming);
        cudaEventCreateWithFlags(&evJoin, cudaEventDisableTiming);
    }

    cudaFuncSetAttribute(gin_gemm_mma_kernel,
                         cudaFuncAttributeMaxDynamicSharedMemorySize, SMT);

    // ---- fork: sort chain on s2, GEMM chain on default stream ----
    cudaEventRecord(evFork, 0);
    cudaStreamWaitEvent(s2, evFork, 0);

    // Branch A (default stream): GEMM
    prep_w_kernel<<<32, 256>>>(W);
    int gemm_blocks = (nnodes + 127) / 128;
    gin_gemm_mma_kernel<<<gemm_blocks, 256, SMT>>>(x, bias, eps, out, nnodes);

    // Branch B (s2): counting sort of edges by row
    int nscan = (nnodes + 255) / 256;
    zero_counts_kernel<<<nscan, 256, 0, s2>>>(nnodes);
    hist_kernel<<<1024, 256, 0, s2>>>(row, nedges);
    scan_block_kernel<<<nscan, 256, 0, s2>>>(nnodes);
    scan_sums_kernel<<<1, 512, 0, s2>>>(nscan);
    finalize_starts_kernel<<<nscan, 256, 0, s2>>>(nnodes);
    scatter_kernel<<<1024, 256, 0, s2>>>(vals, row, col, nedges);

    // ---- join, then aggregation ----
    cudaEventRecord(evJoin, s2);
    cudaStreamWaitEvent(0, evJoin, 0);

    int agg_blocks = (nnodes + 7) / 8;
    gin_agg_kernel<<<agg_blocks, 256>>>(out, nnodes);
}

// round 9
// speedup vs baseline: 2.1642x; 1.1011x over previous
#include <cuda_runtime.h>
#include <cuda_fp16.h>
#include <cuda_bf16.h>

#define UNITS 128
#define MAX_NODES 100000
#define MAX_EDGES 1600000

// ------------------------- static scratch (no allocs) -----------------------
__device__ unsigned g_h16[(size_t)MAX_NODES * (UNITS / 2)];  // fp16 h
__device__ int2  g_perm[MAX_EDGES];
__device__ int   g_counts[MAX_NODES];
__device__ int   g_starts[MAX_NODES];
__device__ int   g_cursor[MAX_NODES];
__device__ int   g_bsums[512];
// W transposed + bf16 split, plain [n][k] row-major, packed 2 bf16 per u32
__device__ unsigned g_Bhi[8192];   // Bt_hi[n][k]
__device__ unsigned g_Blo[8192];   // Bt_lo[n][k]

// ------------------------- helpers ------------------------------------------
__device__ __forceinline__ unsigned pack_h2(float a, float b) {
    unsigned r;
    asm("cvt.rn.f16x2.f32 %0, %1, %2;" : "=r"(r) : "f"(b), "f"(a));
    return r;
}
__device__ __forceinline__ float2 unpack_h2(unsigned u) {
    __half2 h = *(__half2*)&u;
    return __half22float2(h);
}
__device__ __forceinline__ unsigned short bf16bits(float f) {
    __nv_bfloat16 h = __float2bfloat16(f);
    return *(unsigned short*)&h;
}
__device__ __forceinline__ float bf16val(float f) {
    return __bfloat162float(__float2bfloat16(f));
}
__device__ __forceinline__ unsigned smem_u32(const void* p) {
    unsigned a;
    asm("{ .reg .u64 t; cvta.to.shared.u64 t, %1; cvt.u32.u64 %0, t; }" : "=r"(a) : "l"(p));
    return a;
}
__device__ __forceinline__ void ldsm_x4(unsigned& r0, unsigned& r1,
                                        unsigned& r2, unsigned& r3, unsigned addr) {
    asm volatile("ldmatrix.sync.aligned.m8n8.x4.shared.b16 {%0,%1,%2,%3}, [%4];"
                 : "=r"(r0), "=r"(r1), "=r"(r2), "=r"(r3) : "r"(addr));
}
__device__ __forceinline__ void mma_bf16(float* c, const unsigned* a,
                                         unsigned b0, unsigned b1) {
    asm volatile(
        "mma.sync.aligned.m16n8k16.row.col.f32.bf16.bf16.f32 "
        "{%0,%1,%2,%3}, {%4,%5,%6,%7}, {%8,%9}, {%0,%1,%2,%3};"
        : "+f"(c[0]), "+f"(c[1]), "+f"(c[2]), "+f"(c[3])
        : "r"(a[0]), "r"(a[1]), "r"(a[2]), "r"(a[3]), "r"(b0), "r"(b1));
}

// ---------------------------------------------------------------------------
// W prep: g_B{hi,lo}[n*64 + k/2] = bf16 split of W[k][n] (Bt row-major [n][k])
// ---------------------------------------------------------------------------
__global__ void __launch_bounds__(256) prep_w_kernel(const float* __restrict__ W)
{
    int idx = blockIdx.x * blockDim.x + threadIdx.x;   // 8192 items
    if (idx >= 8192) return;
    int n = idx >> 6;
    int j = idx & 63;
    int k = 2 * j;
    float w0 = W[(size_t)k * UNITS + n];
    float w1 = W[(size_t)(k + 1) * UNITS + n];
    unsigned hi = (unsigned)bf16bits(w0) | ((unsigned)bf16bits(w1) << 16);
    unsigned lo = (unsigned)bf16bits(w0 - bf16val(w0)) |
                  ((unsigned)bf16bits(w1 - bf16val(w1)) << 16);
    g_Bhi[idx] = hi;
    g_Blo[idx] = lo;
}

// ---------------------------------------------------------------------------
// mma.sync bf16 GEMM: h = x @ W (3-term split); writes g_h16 (fp16) only.
// Block: 128 rows x 128 cols, 256 threads (8 warps, warp tile 64x32).
// ---------------------------------------------------------------------------
#define ROWB 272
#define TILEB (128 * ROWB)             // 34816 per buffer
#define SMT (4 * TILEB)                // A_hi, A_lo, B_hi, B_lo

__global__ void __launch_bounds__(256) gin_gemm_mma_kernel(
    const float* __restrict__ x, int nrows)
{
    extern __shared__ __align__(128) char smem[];
    const unsigned sbase = smem_u32(smem);
    const unsigned sAhi = sbase;
    const unsigned sAlo = sbase + TILEB;
    const unsigned sBhi = sbase + 2 * TILEB;
    const unsigned sBlo = sbase + 3 * TILEB;

    const int tid = threadIdx.x;
    const int wid = tid >> 5;
    const int lane = tid & 31;
    const int row0 = blockIdx.x * 128;

    // ---- copy Bt splits into padded smem: 16 uint4 per row, 2048 total ----
    {
        const uint4* gh = (const uint4*)g_Bhi;
        const uint4* gl = (const uint4*)g_Blo;
#pragma unroll
        for (int i = 0; i < 8; i++) {
            int j = tid + i * 256;
            int n = j >> 4, c16 = j & 15;
            unsigned dst = n * ROWB + c16 * 16;
            *(uint4*)(smem + 2 * TILEB + dst) = gh[j];
            *(uint4*)(smem + 3 * TILEB + dst) = gl[j];
        }
    }

    // ---- load x, split into bf16 hi/lo, store padded rows ----
#pragma unroll
    for (int it = 0; it < 16; it++) {
        int idx = tid + it * 256;
        int r = idx >> 5;
        int q = idx & 31;
        int gr = row0 + r;
        float4 v = make_float4(0.f, 0.f, 0.f, 0.f);
        if (gr < nrows) v = *(const float4*)&x[(size_t)gr * UNITS + q * 4];
        unsigned h01 = (unsigned)bf16bits(v.x) | ((unsigned)bf16bits(v.y) << 16);
        unsigned h23 = (unsigned)bf16bits(v.z) | ((unsigned)bf16bits(v.w) << 16);
        unsigned l01 = (unsigned)bf16bits(v.x - bf16val(v.x)) |
                       ((unsigned)bf16bits(v.y - bf16val(v.y)) << 16);
        unsigned l23 = (unsigned)bf16bits(v.z - bf16val(v.z)) |
                       ((unsigned)bf16bits(v.w - bf16val(v.w)) << 16);
        unsigned dst = r * ROWB + q * 8;
        *(uint2*)(smem + dst) = make_uint2(h01, h23);                    // A_hi
        *(uint2*)(smem + TILEB + dst) = make_uint2(l01, l23);            // A_lo
    }
    __syncthreads();

    const int wm = (wid >> 2) * 64;
    const int wn = (wid & 3) * 32;
    const int msub = lane >> 3;
    const int mr   = lane & 7;

    float acc[4][4][4];
#pragma unroll
    for (int mi = 0; mi < 4; mi++)
#pragma unroll
        for (int ni = 0; ni < 4; ni++)
#pragma unroll
            for (int c = 0; c < 4; c++) acc[mi][ni][c] = 0.f;

#pragma unroll
    for (int term = 0; term < 3; term++) {
        const unsigned Asrc = (term == 2) ? sAlo : sAhi;
        const unsigned Bsrc = (term == 1) ? sBlo : sBhi;
#pragma unroll
        for (int ks = 0; ks < 8; ks++) {
            const int k0 = ks * 16;
            unsigned a[4][4];
#pragma unroll
            for (int mi = 0; mi < 4; mi++) {
                int arow = wm + mi * 16 + (msub & 1) * 8 + mr;
                int acolb = (k0 + (msub >> 1) * 8) * 2;
                ldsm_x4(a[mi][0], a[mi][1], a[mi][2], a[mi][3],
                        Asrc + arow * ROWB + acolb);
            }
            unsigned b[2][4];
#pragma unroll
            for (int nb = 0; nb < 2; nb++) {
                int brow = wn + nb * 16 + (msub >> 1) * 8 + mr;
                int bcolb = (k0 + (msub & 1) * 8) * 2;
                ldsm_x4(b[nb][0], b[nb][1], b[nb][2], b[nb][3],
                        Bsrc + brow * ROWB + bcolb);
            }
#pragma unroll
            for (int mi = 0; mi < 4; mi++)
#pragma unroll
                for (int ni = 0; ni < 4; ni++)
                    mma_bf16(acc[mi][ni], a[mi],
                             b[ni >> 1][(ni & 1) * 2], b[ni >> 1][(ni & 1) * 2 + 1]);
        }
    }

    // ---- epilogue: fp16 h only ----
    const int g   = lane >> 2;
    const int tig = lane & 3;
#pragma unroll
    for (int mi = 0; mi < 4; mi++) {
#pragma unroll
        for (int half = 0; half < 2; half++) {
            int gr = row0 + wm + mi * 16 + g + half * 8;
            if (gr >= nrows) continue;
#pragma unroll
            for (int ni = 0; ni < 4; ni++) {
                int col = wn + ni * 8 + tig * 2;
                g_h16[(size_t)gr * 64 + (col >> 1)] =
                    pack_h2(acc[mi][ni][half * 2], acc[mi][ni][half * 2 + 1]);
            }
        }
    }
}

// ---------------------------------------------------------------------------
// Counting sort of edges by destination row
// ---------------------------------------------------------------------------
__global__ void __launch_bounds__(256) zero_counts_kernel(int n)
{
    int i = blockIdx.x * blockDim.x + threadIdx.x;
    int stride = gridDim.x * blockDim.x;
    for (; i < n; i += stride) g_counts[i] = 0;
}

__global__ void __launch_bounds__(256) hist_kernel(const int* __restrict__ row, int nedges)
{
    int i = blockIdx.x * blockDim.x + threadIdx.x;
    int stride = gridDim.x * blockDim.x;
    for (; i < nedges; i += stride) atomicAdd(&g_counts[row[i]], 1);
}

__global__ void __launch_bounds__(256) scan_block_kernel(int n)
{
    __shared__ int sh[256];
    int i = blockIdx.x * 256 + threadIdx.x;
    int v = (i < n) ? g_counts[i] : 0;
    sh[threadIdx.x] = v;
    __syncthreads();
#pragma unroll
    for (int off = 1; off < 256; off <<= 1) {
        int t = (threadIdx.x >= off) ? sh[threadIdx.x - off] : 0;
        __syncthreads();
        sh[threadIdx.x] += t;
        __syncthreads();
    }
    if (i < n) g_starts[i] = sh[threadIdx.x] - v;
    if (threadIdx.x == 255) g_bsums[blockIdx.x] = sh[255];
}

__global__ void __launch_bounds__(512) scan_sums_kernel(int nb)
{
    __shared__ int sh[512];
    int t = threadIdx.x;
    int v = (t < nb) ? g_bsums[t] : 0;
    sh[t] = v;
    __syncthreads();
#pragma unroll
    for (int off = 1; off < 512; off <<= 1) {
        int u = (t >= off) ? sh[t - off] : 0;
        __syncthreads();
        sh[t] += u;
        __syncthreads();
    }
    if (t < nb) g_bsums[t] = sh[t] - v;
}

__global__ void __launch_bounds__(256) finalize_starts_kernel(int n)
{
    int i = blockIdx.x * blockDim.x + threadIdx.x;
    if (i < n) {
        int s = g_starts[i] + g_bsums[i >> 8];
        g_starts[i] = s;
        g_cursor[i] = s;
    }
}

__global__ void __launch_bounds__(256) scatter_kernel(
    const float* __restrict__ vals, const int* __restrict__ row,
    const int* __restrict__ col, int nedges)
{
    int i = blockIdx.x * blockDim.x + threadIdx.x;
    int stride = gridDim.x * blockDim.x;
    for (; i < nedges; i += stride) {
        int r = row[i];
        int p = atomicAdd(&g_cursor[r], 1);
        g_perm[p] = make_int2(col[i], __float_as_int(vals[i]));
    }
}

// ---------------------------------------------------------------------------
// Warp-per-node aggregation + fused base + relu:
// out = relu((1+eps)*h16[node] + bias + sum vals*h16[col])
// ---------------------------------------------------------------------------
__global__ void __launch_bounds__(256) gin_agg_kernel(
    float* __restrict__ out, const float* __restrict__ bias,
    const float* __restrict__ eps, int nnodes)
{
    const int node = (blockIdx.x * blockDim.x + threadIdx.x) >> 5;
    if (node >= nnodes) return;
    const int lane = threadIdx.x & 31;

    const int s   = g_starts[node];
    const int end = s + g_counts[node];

    float4 acc[4];
#pragma unroll
    for (int j = 0; j < 4; j++) acc[j] = make_float4(0.f, 0.f, 0.f, 0.f);

    int e = s;
    // 8-edge batches: 8 independent gathers in flight per lane
    for (; e + 8 <= end; e += 8) {
        int2 p[8];
#pragma unroll
        for (int j = 0; j < 8; j++) p[j] = g_perm[e + j];
        uint2 raw[8];
#pragma unroll
        for (int j = 0; j < 8; j++)
            raw[j] = *(const uint2*)&g_h16[(size_t)p[j].x * (UNITS / 2) + lane * 2];
#pragma unroll
        for (int j = 0; j < 8; j++) {
            float v = __int_as_float(p[j].y);
            float2 fa = unpack_h2(raw[j].x);
            float2 fb = unpack_h2(raw[j].y);
            acc[j & 3].x = fmaf(v, fa.x, acc[j & 3].x);
            acc[j & 3].y = fmaf(v, fa.y, acc[j & 3].y);
            acc[j & 3].z = fmaf(v, fb.x, acc[j & 3].z);
            acc[j & 3].w = fmaf(v, fb.y, acc[j & 3].w);
        }
    }
    for (; e + 4 <= end; e += 4) {
        int2 p[4];
#pragma unroll
        for (int j = 0; j < 4; j++) p[j] = g_perm[e + j];
        uint2 raw[4];
#pragma unroll
        for (int j = 0; j < 4; j++)
            raw[j] = *(const uint2*)&g_h16[(size_t)p[j].x * (UNITS / 2) + lane * 2];
#pragma unroll
        for (int j = 0; j < 4; j++) {
            float v = __int_as_float(p[j].y);
            float2 fa = unpack_h2(raw[j].x);
            float2 fb = unpack_h2(raw[j].y);
            acc[j].x = fmaf(v, fa.x, acc[j].x);
            acc[j].y = fmaf(v, fa.y, acc[j].y);
            acc[j].z = fmaf(v, fb.x, acc[j].z);
            acc[j].w = fmaf(v, fb.y, acc[j].w);
        }
    }
    for (; e < end; e++) {
        int2 p = g_perm[e];
        uint2 raw = *(const uint2*)&g_h16[(size_t)p.x * (UNITS / 2) + lane * 2];
        float v = __int_as_float(p.y);
        float2 fa = unpack_h2(raw.x);
        float2 fb = unpack_h2(raw.y);
        acc[0].x = fmaf(v, fa.x, acc[0].x);
        acc[0].y = fmaf(v, fa.y, acc[0].y);
        acc[0].z = fmaf(v, fb.x, acc[0].z);
        acc[0].w = fmaf(v, fb.y, acc[0].w);
    }

    // base term from own h row (fp16) + bias, then relu
    const float e1 = 1.0f + eps[0];
    uint2 own = *(const uint2*)&g_h16[(size_t)node * (UNITS / 2) + lane * 2];
    float2 ha = unpack_h2(own.x);
    float2 hb = unpack_h2(own.y);
    float4 bv = *(const float4*)&bias[lane * 4];

    float4 o;
    o.x = fmaxf(fmaf(e1, ha.x, bv.x) + acc[0].x + acc[1].x + acc[2].x + acc[3].x, 0.f);
    o.y = fmaxf(fmaf(e1, ha.y, bv.y) + acc[0].y + acc[1].y + acc[2].y + acc[3].y, 0.f);
    o.z = fmaxf(fmaf(e1, hb.x, bv.z) + acc[0].z + acc[1].z + acc[2].z + acc[3].z, 0.f);
    o.w = fmaxf(fmaf(e1, hb.y, bv.w) + acc[0].w + acc[1].w + acc[2].w + acc[3].w, 0.f);
    *(float4*)&out[(size_t)node * UNITS + lane * 4] = o;
}

// ---------------------------------------------------------------------------
extern "C" void kernel_launch(void* const* d_in, const int* in_sizes, int n_in,
                              void* d_out, int out_size)
{
    const float* x    = (const float*)d_in[0];
    const float* W    = (const float*)d_in[1];
    const float* bias = (const float*)d_in[2];
    const float* eps  = (const float*)d_in[3];
    const float* vals = (const float*)d_in[4];
    const int*   row  = (const int*)d_in[5];
    const int*   col  = (const int*)d_in[6];
    float* out = (float*)d_out;

    const int nnodes = in_sizes[0] / UNITS;
    const int nedges = in_sizes[4];

    static cudaStream_t s2 = nullptr;
    static cudaEvent_t evFork = nullptr, evJoin = nullptr;
    if (s2 == nullptr) {
        cudaStreamCreateWithFlags(&s2, cudaStreamNonBlocking);
        cudaEventCreateWithFlags(&evFork, cudaEventDisableTiming);
        cudaEventCreateWithFlags(&evJoin, cudaEventDisableTiming);
    }

    cudaFuncSetAttribute(gin_gemm_mma_kernel,
                         cudaFuncAttributeMaxDynamicSharedMemorySize, SMT);

    // ---- fork: sort chain on s2, GEMM chain on default stream ----
    cudaEventRecord(evFork, 0);
    cudaStreamWaitEvent(s2, evFork, 0);

    // Branch A (default stream): GEMM (writes g_h16 only)
    prep_w_kernel<<<32, 256>>>(W);
    int gemm_blocks = (nnodes + 127) / 128;
    gin_gemm_mma_kernel<<<gemm_blocks, 256, SMT>>>(x, nnodes);

    // Branch B (s2): counting sort of edges by row
    int nscan = (nnodes + 255) / 256;
    zero_counts_kernel<<<nscan, 256, 0, s2>>>(nnodes);
    hist_kernel<<<1024, 256, 0, s2>>>(row, nedges);
    scan_block_kernel<<<nscan, 256, 0, s2>>>(nnodes);
    scan_sums_kernel<<<1, 512, 0, s2>>>(nscan);
    finalize_starts_kernel<<<nscan, 256, 0, s2>>>(nnodes);
    scatter_kernel<<<1024, 256, 0, s2>>>(vals, row, col, nedges);

    // ---- join, then aggregation (base + agg + relu fused) ----
    cudaEventRecord(evJoin, s2);
    cudaStreamWaitEvent(0, evJoin, 0);

    int agg_blocks = (nnodes + 7) / 8;
    gin_agg_kernel<<<agg_blocks, 256>>>(out, bias, eps, nnodes);
}